// round 14
// baseline (speedup 1.0000x reference)
#include <cuda_runtime.h>
#include <cuda_fp16.h>
#include <mma.h>

using namespace nvcuda;

#define N_NODES 50000
#define N_EDGES 800000
#define D 128
#define N_PAD 50048              // 782 * 64, padded row count for guard-free GEMM
#define SCAN_BLK 196             // ceil(50000/256)
#define N_CHUNK 4
#define CHUNK_ROWS 12544         // 196 gemm blocks of 64 rows

// ---- scratch (device globals; no allocation allowed) ----
__device__ __half g_a  [N_PAD * D];     // 12.8 MB: layer-2 GEMM input (pre-scaled by dinv)
__device__ __half g_xsh[N_PAD * D];     // 12.8 MB: layer-1 GEMM output (messages)
__device__ __half g_b  [N_PAD * D];     // 12.8 MB: layer-2 GEMM output (ping buffer —
                                        //   must NOT alias g_xsh: gather-1 chunks still
                                        //   read arbitrary g_xsh rows while gemm-2 runs)
__device__ __half g_w1 [D * D];
__device__ __half g_w2 [D * D];
__device__ float  g_dinv[N_NODES];
__device__ int    g_deg [N_NODES];
__device__ int    g_off [N_NODES + 1];
__device__ int    g_cur [N_NODES];
__device__ int    g_csr [N_EDGES];      // source node per incoming edge, grouped by target
__device__ int    g_bsum[SCAN_BLK];
__device__ int    g_boff[SCAN_BLK];

// ---------------------------------------------------------------------------
__global__ void k_hist(const int4* __restrict__ col4) {
    int i = blockIdx.x * blockDim.x + threadIdx.x;
    if (i < N_EDGES / 4) {
        int4 c = __ldg(&col4[i]);
        atomicAdd(&g_deg[c.x], 1);
        atomicAdd(&g_deg[c.y], 1);
        atomicAdd(&g_deg[c.z], 1);
        atomicAdd(&g_deg[c.w], 1);
    }
}

// --- parallel scan: block sums -> scan sums -> apply -------------------------
__global__ void k_bsum() {
    __shared__ int sh[256];
    int t = threadIdx.x;
    int i = blockIdx.x * 256 + t;
    sh[t] = (i < N_NODES) ? g_deg[i] : 0;
    __syncthreads();
#pragma unroll
    for (int d = 128; d > 0; d >>= 1) {
        if (t < d) sh[t] += sh[t + d];
        __syncthreads();
    }
    if (t == 0) g_bsum[blockIdx.x] = sh[0];
}

__global__ void k_scan_b() {        // 1 block, 256 threads, scan 196 block sums
    __shared__ int sh[256];
    int t = threadIdx.x;
    int v = (t < SCAN_BLK) ? g_bsum[t] : 0;
    sh[t] = v;
    __syncthreads();
    for (int d = 1; d < 256; d <<= 1) {
        int u = 0;
        if (t >= d) u = sh[t - d];
        __syncthreads();
        if (t >= d) sh[t] += u;
        __syncthreads();
    }
    if (t < SCAN_BLK) g_boff[t] = sh[t] - v;   // exclusive
}

__global__ void k_apply() {
    __shared__ int sh[256];
    int t = threadIdx.x;
    int i = blockIdx.x * 256 + t;
    int dg = (i < N_NODES) ? g_deg[i] : 0;
    sh[t] = dg;
    __syncthreads();
    for (int d = 1; d < 256; d <<= 1) {
        int u = 0;
        if (t >= d) u = sh[t - d];
        __syncthreads();
        if (t >= d) sh[t] += u;
        __syncthreads();
    }
    if (i < N_NODES) {
        int excl = sh[t] - dg + g_boff[blockIdx.x];
        g_off[i] = excl;
        g_cur[i] = excl;
        g_dinv[i] = rsqrtf((float)(dg + 1));   // +1 self loop -> always > 0
        if (i == N_NODES - 1) g_off[N_NODES] = excl + dg;
    }
}

__global__ void k_build_csr(const int4* __restrict__ row4, const int4* __restrict__ col4) {
    int i = blockIdx.x * blockDim.x + threadIdx.x;
    if (i < N_EDGES / 4) {
        int4 r = __ldg(&row4[i]);
        int4 c = __ldg(&col4[i]);
        g_csr[atomicAdd(&g_cur[c.x], 1)] = r.x;
        g_csr[atomicAdd(&g_cur[c.y], 1)] = r.y;
        g_csr[atomicAdd(&g_cur[c.z], 1)] = r.z;
        g_csr[atomicAdd(&g_cur[c.w], 1)] = r.w;
    }
}

// ---------------------------------------------------------------------------
__global__ void k_conv_w(const float* __restrict__ W1, const float* __restrict__ W2) {
    int i = blockIdx.x * blockDim.x + threadIdx.x;
    if (i < D * D) {
        g_w1[i] = __float2half_rn(W1[i]);
        g_w2[i] = __float2half_rn(W2[i]);
    }
}

// ---------------------------------------------------------------------------
// Tensor-core GEMM, fp16 input from global: out = A @ W.
// Block = 64 rows x 128 cols, 8 warps 2x4, warp tile 32x32.
__global__ void __launch_bounds__(256)
k_gemm_wmma(const __half* __restrict__ A, const __half* __restrict__ W,
            __half* __restrict__ out) {
    __shared__ float Cs[64][132];

    const int wid = threadIdx.x >> 5;
    const int wr  = wid >> 2;
    const int wc  = wid & 3;
    const int row0 = blockIdx.x * 64 + wr * 32;
    const int col0 = wc * 32;

    wmma::fragment<wmma::accumulator, 16, 16, 16, float> acc[2][2];
#pragma unroll
    for (int i = 0; i < 2; i++)
#pragma unroll
        for (int j = 0; j < 2; j++) wmma::fill_fragment(acc[i][j], 0.0f);

#pragma unroll
    for (int k = 0; k < D; k += 16) {
        wmma::fragment<wmma::matrix_a, 16, 16, 16, __half, wmma::row_major> a0, a1;
        wmma::fragment<wmma::matrix_b, 16, 16, 16, __half, wmma::row_major> b0, b1;
        wmma::load_matrix_sync(a0, A + (size_t)row0 * D + k, D);
        wmma::load_matrix_sync(a1, A + (size_t)(row0 + 16) * D + k, D);
        wmma::load_matrix_sync(b0, W + (size_t)k * D + col0, D);
        wmma::load_matrix_sync(b1, W + (size_t)k * D + col0 + 16, D);
        wmma::mma_sync(acc[0][0], a0, b0, acc[0][0]);
        wmma::mma_sync(acc[0][1], a0, b1, acc[0][1]);
        wmma::mma_sync(acc[1][0], a1, b0, acc[1][0]);
        wmma::mma_sync(acc[1][1], a1, b1, acc[1][1]);
    }

#pragma unroll
    for (int i = 0; i < 2; i++)
#pragma unroll
        for (int j = 0; j < 2; j++)
            wmma::store_matrix_sync(&Cs[wr * 32 + i * 16][col0 + j * 16],
                                    acc[i][j], 132, wmma::mem_row_major);
    __syncthreads();

    const size_t outBase = (size_t)blockIdx.x * 64 * D;
    for (int g = threadIdx.x; g < 64 * 32; g += 256) {
        int r  = g >> 5;
        int c4 = (g & 31) * 4;
        union { __half2 h2[2]; uint2 u; } pk;
        pk.h2[0] = __floats2half2_rn(Cs[r][c4 + 0], Cs[r][c4 + 1]);
        pk.h2[1] = __floats2half2_rn(Cs[r][c4 + 2], Cs[r][c4 + 3]);
        *(uint2*)&out[outBase + (size_t)r * D + c4] = pk.u;
    }
}

// Layer-1 GEMM: fp32 A converted to fp16 in a smem staging tile; As/Cs union
// keeps static smem at 33.8 KB.
__global__ void __launch_bounds__(256)
k_gemm_wmma_f32(const float* __restrict__ A, const __half* __restrict__ W,
                __half* __restrict__ out) {
    __shared__ union SmemU {
        __half As[64][136];   // 17408 B
        float  Cs[64][132];   // 33792 B
    } sm;

    const int tid = threadIdx.x;
    const int wid = tid >> 5;
    const int wr  = wid >> 2;
    const int wc  = wid & 3;
    const int rowBase = blockIdx.x * 64;
    const int col0 = wc * 32;

    {
        int r  = tid >> 2;            // 0..63
        int c0 = (tid & 3) * 32;      // 0,32,64,96
        int grow = rowBase + r;
        if (grow < N_NODES) {
            const float* src = A + (size_t)grow * D + c0;
#pragma unroll
            for (int q = 0; q < 8; q++) {
                float4 v = *(const float4*)(src + q * 4);
                union { __half2 h2[2]; uint2 u; } pk;
                pk.h2[0] = __floats2half2_rn(v.x, v.y);
                pk.h2[1] = __floats2half2_rn(v.z, v.w);
                *(uint2*)&sm.As[r][c0 + q * 4] = pk.u;
            }
        } else {
            uint2 z = make_uint2(0, 0);
#pragma unroll
            for (int q = 0; q < 8; q++) *(uint2*)&sm.As[r][c0 + q * 4] = z;
        }
    }
    __syncthreads();

    wmma::fragment<wmma::accumulator, 16, 16, 16, float> acc[2][2];
#pragma unroll
    for (int i = 0; i < 2; i++)
#pragma unroll
        for (int j = 0; j < 2; j++) wmma::fill_fragment(acc[i][j], 0.0f);

#pragma unroll
    for (int k = 0; k < D; k += 16) {
        wmma::fragment<wmma::matrix_a, 16, 16, 16, __half, wmma::row_major> a0, a1;
        wmma::fragment<wmma::matrix_b, 16, 16, 16, __half, wmma::row_major> b0, b1;
        wmma::load_matrix_sync(a0, &sm.As[wr * 32][k], 136);
        wmma::load_matrix_sync(a1, &sm.As[wr * 32 + 16][k], 136);
        wmma::load_matrix_sync(b0, W + (size_t)k * D + col0, D);
        wmma::load_matrix_sync(b1, W + (size_t)k * D + col0 + 16, D);
        wmma::mma_sync(acc[0][0], a0, b0, acc[0][0]);
        wmma::mma_sync(acc[0][1], a0, b1, acc[0][1]);
        wmma::mma_sync(acc[1][0], a1, b0, acc[1][0]);
        wmma::mma_sync(acc[1][1], a1, b1, acc[1][1]);
    }
    __syncthreads();   // WAR fence: all As reads done before Cs overwrites the union

#pragma unroll
    for (int i = 0; i < 2; i++)
#pragma unroll
        for (int j = 0; j < 2; j++)
            wmma::store_matrix_sync(&sm.Cs[wr * 32 + i * 16][col0 + j * 16],
                                    acc[i][j], 132, wmma::mem_row_major);
    __syncthreads();

    const size_t outBase = (size_t)blockIdx.x * 64 * D;
    for (int g = tid; g < 64 * 32; g += 256) {
        int r  = g >> 5;
        int c4 = (g & 31) * 4;
        union { __half2 h2[2]; uint2 u; } pk;
        pk.h2[0] = __floats2half2_rn(sm.Cs[r][c4 + 0], sm.Cs[r][c4 + 1]);
        pk.h2[1] = __floats2half2_rn(sm.Cs[r][c4 + 2], sm.Cs[r][c4 + 3]);
        *(uint2*)&out[outBase + (size_t)r * D + c4] = pk.u;
    }
}

// ---------------------------------------------------------------------------
// Load 8 consecutive fp16 features (16 B) of row r at half-offset c8 as floats.
__device__ __forceinline__ void ld_row8(const __half* __restrict__ xs, int r, int c8,
                                        float* v) {
    uint4 u = __ldg((const uint4*)(xs + (size_t)r * D + c8));
    const __half2* h = (const __half2*)&u;
#pragma unroll
    for (int q = 0; q < 4; q++) {
        float2 f = __half22float2(h[q]);
        v[2 * q]     = f.x;
        v[2 * q + 1] = f.y;
    }
}

// Gather: one warp per node. Each half-warp covers the full 128-feature row
// with 16 lanes x 16 B and processes alternating edges (2 edges in flight per
// warp, x2 unroll = 4 independent row streams). Halves combine via shfl_xor(16).
// SRC_SCALE: multiply each message by dinv[src].
// OUT_HALF : write fp16(result * dinv[node]) as next layer's GEMM input.
template <bool SRC_SCALE, bool OUT_HALF>
__global__ void k_gather(const __half* __restrict__ xs, const float* __restrict__ b,
                         const float* __restrict__ a, float* __restrict__ outf,
                         __half* __restrict__ outh, int nodeBase, int nNodes) {
    int w = (blockIdx.x * blockDim.x + threadIdx.x) >> 5;
    if (w >= nNodes) return;
    const int node = nodeBase + w;
    const int lane = threadIdx.x & 31;
    const int half = lane >> 4;
    const int c8   = (lane & 15) * 8;      // half-element offset, 16 B
    const float di = g_dinv[node];

    float acc[8];
    if (half == 0) {                        // self loop counted once
        float sv[8];
        ld_row8(xs, node, c8, sv);
        float sw = SRC_SCALE ? di : 1.0f;
#pragma unroll
        for (int q = 0; q < 8; q++) acc[q] = sv[q] * sw;
    } else {
#pragma unroll
        for (int q = 0; q < 8; q++) acc[q] = 0.0f;
    }

    const int s = g_off[node];
    const int e = g_off[node + 1];
    int i = s + half;                       // this half's first edge
    for (; i + 2 < e; i += 4) {             // 2 edges per half per iter
        int r0 = __ldg(&g_csr[i]);
        int r1 = __ldg(&g_csr[i + 2]);
        float v0[8], v1[8];
        ld_row8(xs, r0, c8, v0);
        ld_row8(xs, r1, c8, v1);
        float w0 = SRC_SCALE ? __ldg(&g_dinv[r0]) : 1.0f;
        float w1 = SRC_SCALE ? __ldg(&g_dinv[r1]) : 1.0f;
#pragma unroll
        for (int q = 0; q < 8; q++)
            acc[q] = fmaf(v0[q], w0, fmaf(v1[q], w1, acc[q]));
    }
    if (i < e) {
        int r0 = __ldg(&g_csr[i]);
        float v0[8];
        ld_row8(xs, r0, c8, v0);
        float w0 = SRC_SCALE ? __ldg(&g_dinv[r0]) : 1.0f;
#pragma unroll
        for (int q = 0; q < 8; q++) acc[q] = fmaf(v0[q], w0, acc[q]);
    }

    // combine halves (same c8 in both halves)
#pragma unroll
    for (int q = 0; q < 8; q++)
        acc[q] += __shfl_xor_sync(0xffffffffu, acc[q], 16);

    if (half == 0) {
        float4 b0 = *(const float4*)&b[c8];
        float4 b1 = *(const float4*)&b[c8 + 4];
        float4 a0 = *(const float4*)&a[c8];
        float4 a1 = *(const float4*)&a[c8 + 4];
        float bb[8] = {b0.x, b0.y, b0.z, b0.w, b1.x, b1.y, b1.z, b1.w};
        float aa[8] = {a0.x, a0.y, a0.z, a0.w, a1.x, a1.y, a1.z, a1.w};
        float o[8];
#pragma unroll
        for (int q = 0; q < 8; q++) {
            o[q] = fmaf(di, acc[q], bb[q]);
            o[q] = (o[q] >= 0.f) ? o[q] : aa[q] * o[q];
        }
        if (OUT_HALF) {
            union { __half2 h2[4]; uint4 u; } pk;
#pragma unroll
            for (int q = 0; q < 4; q++)
                pk.h2[q] = __floats2half2_rn(o[2 * q] * di, o[2 * q + 1] * di);
            *(uint4*)&outh[(size_t)node * D + c8] = pk.u;
        } else {
            *(float4*)&outf[(size_t)node * D + c8]     = make_float4(o[0], o[1], o[2], o[3]);
            *(float4*)&outf[(size_t)node * D + c8 + 4] = make_float4(o[4], o[5], o[6], o[7]);
        }
    }
}

// ---------------------------------------------------------------------------
extern "C" void kernel_launch(void* const* d_in, const int* in_sizes, int n_in,
                              void* d_out, int out_size) {
    const float* x  = (const float*)d_in[0];
    const int*   ei = (const int*)  d_in[1];
    const float* W1 = (const float*)d_in[2];
    const float* b1 = (const float*)d_in[3];
    const float* a1 = (const float*)d_in[4];
    const float* W2 = (const float*)d_in[5];
    const float* b2 = (const float*)d_in[6];
    const float* a2 = (const float*)d_in[7];
    float* out = (float*)d_out;

    const int4* row4 = (const int4*)ei;               // edge_index[0] = sources
    const int4* col4 = (const int4*)(ei + N_EDGES);   // edge_index[1] = targets

    __half *a_ptr, *xs_ptr, *b_ptr, *w1_ptr, *w2_ptr;  int *deg_ptr;
    cudaGetSymbolAddress((void**)&a_ptr,   g_a);
    cudaGetSymbolAddress((void**)&xs_ptr,  g_xsh);
    cudaGetSymbolAddress((void**)&b_ptr,   g_b);
    cudaGetSymbolAddress((void**)&w1_ptr,  g_w1);
    cudaGetSymbolAddress((void**)&w2_ptr,  g_w2);
    cudaGetSymbolAddress((void**)&deg_ptr, g_deg);

    // one-time stream/event setup (host resources only; created on the first,
    // uncaptured call — never during graph capture)
    static cudaStream_t s_side = nullptr;
    static cudaEvent_t  ev_fork = nullptr, ev_g1 = nullptr;
    static cudaEvent_t  ev_c[N_CHUNK] = {nullptr, nullptr, nullptr, nullptr};
    if (s_side == nullptr)  cudaStreamCreateWithFlags(&s_side, cudaStreamNonBlocking);
    if (ev_fork == nullptr) cudaEventCreateWithFlags(&ev_fork, cudaEventDisableTiming);
    if (ev_g1 == nullptr)   cudaEventCreateWithFlags(&ev_g1, cudaEventDisableTiming);
    for (int i = 0; i < N_CHUNK; i++)
        if (ev_c[i] == nullptr) cudaEventCreateWithFlags(&ev_c[i], cudaEventDisableTiming);

    const int e4blocks    = (N_EDGES / 4 + 255) / 256;
    const int gemm_blocks = N_PAD / 64;   // 782

    // ---- fork: CSR chain on side stream (independent of GEMM-1) ----
    cudaEventRecord(ev_fork, 0);
    cudaStreamWaitEvent(s_side, ev_fork, 0);
    cudaMemsetAsync(deg_ptr, 0, N_NODES * sizeof(int), s_side);
    k_hist     <<<e4blocks, 256, 0, s_side>>>(col4);
    k_bsum     <<<SCAN_BLK, 256, 0, s_side>>>();
    k_scan_b   <<<1, 256, 0, s_side>>>();
    k_apply    <<<SCAN_BLK, 256, 0, s_side>>>();
    k_build_csr<<<e4blocks, 256, 0, s_side>>>(row4, col4);

    // ---- main stream: weight convert + layer-1 GEMM (no dinv needed) ----
    k_conv_w       <<<(D * D + 255) / 256, 256>>>(W1, W2);
    k_gemm_wmma_f32<<<gemm_blocks, 256>>>(x, w1_ptr, xs_ptr);
    cudaEventRecord(ev_g1, 0);

    // ---- pipelined: gather-1 chunks (side stream) feed gemm-2 chunks (main).
    //      gather-1 reads xs (all rows) + writes g_a (own rows);
    //      gemm-2 reads g_a (chunk rows, event-ordered) + writes g_b (disjoint
    //      from xs, so in-flight gather-1 chunks are unaffected). ----
    cudaStreamWaitEvent(s_side, ev_g1, 0);   // side: CSR done in-stream; wait for xs
    for (int c = 0; c < N_CHUNK; c++) {
        int start  = c * CHUNK_ROWS;
        int nNodes = (start + CHUNK_ROWS <= N_NODES) ? CHUNK_ROWS : (N_NODES - start);
        int gblk   = (nNodes + 7) / 8;       // 8 warps per 256-thread block
        k_gather<true, true><<<gblk, 256, 0, s_side>>>(
            xs_ptr, b1, a1, nullptr, a_ptr, start, nNodes);
        cudaEventRecord(ev_c[c], s_side);

        int rows   = (c == N_CHUNK - 1) ? (N_PAD - start) : CHUNK_ROWS;
        cudaStreamWaitEvent(0, ev_c[c], 0);
        k_gemm_wmma<<<rows / 64, 256>>>(a_ptr + (size_t)start * D, w2_ptr,
                                        b_ptr + (size_t)start * D);
    }

    // ---- final gather (needs all of gemm-2's output in g_b) ----
    k_gather<false, false><<<(N_NODES + 7) / 8, 256>>>(
        b_ptr, b2, a2, out, nullptr, 0, N_NODES);
}

// round 15
// speedup vs baseline: 1.1734x; 1.1734x over previous
#include <cuda_runtime.h>
#include <cuda_fp16.h>
#include <mma.h>

using namespace nvcuda;

#define N_NODES 50000
#define N_EDGES 800000
#define D 128
#define N_PAD 50048              // 782 * 64, padded row count for guard-free GEMM
#define CAP 96                   // bucket capacity per node (deg ~ Poisson(16))

// ---- scratch (device globals; no allocation allowed) ----
__device__ __half g_a  [N_PAD * D];     // 12.8 MB: layer-2 GEMM input (pre-scaled by dinv)
__device__ __half g_xsh[N_PAD * D];     // 12.8 MB: GEMM output (messages)
__device__ __half g_w1 [D * D];
__device__ __half g_w2 [D * D];
__device__ float  g_dinv[N_NODES];
__device__ int    g_cur [N_NODES];      // per-node incoming-edge count (atomic cursor)
__device__ int    g_bkt [N_NODES * CAP]; // 19.2 MB: padded buckets of source nodes

// ---------------------------------------------------------------------------
// Single-pass bucket build: no histogram, no scan. Each incoming edge claims a
// slot in its target's fixed-capacity bucket.
__global__ void k_bucket(const int4* __restrict__ row4, const int4* __restrict__ col4) {
    int i = blockIdx.x * blockDim.x + threadIdx.x;
    if (i < N_EDGES / 4) {
        int4 r = __ldg(&row4[i]);
        int4 c = __ldg(&col4[i]);
        g_bkt[c.x * CAP + atomicAdd(&g_cur[c.x], 1)] = r.x;
        g_bkt[c.y * CAP + atomicAdd(&g_cur[c.y], 1)] = r.y;
        g_bkt[c.z * CAP + atomicAdd(&g_cur[c.z], 1)] = r.z;
        g_bkt[c.w * CAP + atomicAdd(&g_cur[c.w], 1)] = r.w;
    }
}

__global__ void k_dinv() {
    int i = blockIdx.x * blockDim.x + threadIdx.x;
    if (i < N_NODES)
        g_dinv[i] = rsqrtf((float)(g_cur[i] + 1));   // +1 self loop -> always > 0
}

// ---------------------------------------------------------------------------
__global__ void k_conv_w(const float* __restrict__ W1, const float* __restrict__ W2) {
    int i = blockIdx.x * blockDim.x + threadIdx.x;
    if (i < D * D) {
        g_w1[i] = __float2half_rn(W1[i]);
        g_w2[i] = __float2half_rn(W2[i]);
    }
}

// ---------------------------------------------------------------------------
// Tensor-core GEMM, fp16 input from global: out = A @ W.
// Block = 64 rows x 128 cols, 8 warps 2x4, warp tile 32x32.
__global__ void __launch_bounds__(256)
k_gemm_wmma(const __half* __restrict__ A, const __half* __restrict__ W,
            __half* __restrict__ out) {
    __shared__ float Cs[64][132];

    const int wid = threadIdx.x >> 5;
    const int wr  = wid >> 2;
    const int wc  = wid & 3;
    const int row0 = blockIdx.x * 64 + wr * 32;
    const int col0 = wc * 32;

    wmma::fragment<wmma::accumulator, 16, 16, 16, float> acc[2][2];
#pragma unroll
    for (int i = 0; i < 2; i++)
#pragma unroll
        for (int j = 0; j < 2; j++) wmma::fill_fragment(acc[i][j], 0.0f);

#pragma unroll
    for (int k = 0; k < D; k += 16) {
        wmma::fragment<wmma::matrix_a, 16, 16, 16, __half, wmma::row_major> a0, a1;
        wmma::fragment<wmma::matrix_b, 16, 16, 16, __half, wmma::row_major> b0, b1;
        wmma::load_matrix_sync(a0, A + (size_t)row0 * D + k, D);
        wmma::load_matrix_sync(a1, A + (size_t)(row0 + 16) * D + k, D);
        wmma::load_matrix_sync(b0, W + (size_t)k * D + col0, D);
        wmma::load_matrix_sync(b1, W + (size_t)k * D + col0 + 16, D);
        wmma::mma_sync(acc[0][0], a0, b0, acc[0][0]);
        wmma::mma_sync(acc[0][1], a0, b1, acc[0][1]);
        wmma::mma_sync(acc[1][0], a1, b0, acc[1][0]);
        wmma::mma_sync(acc[1][1], a1, b1, acc[1][1]);
    }

#pragma unroll
    for (int i = 0; i < 2; i++)
#pragma unroll
        for (int j = 0; j < 2; j++)
            wmma::store_matrix_sync(&Cs[wr * 32 + i * 16][col0 + j * 16],
                                    acc[i][j], 132, wmma::mem_row_major);
    __syncthreads();

    const size_t outBase = (size_t)blockIdx.x * 64 * D;
    for (int g = threadIdx.x; g < 64 * 32; g += 256) {
        int r  = g >> 5;
        int c4 = (g & 31) * 4;
        union { __half2 h2[2]; uint2 u; } pk;
        pk.h2[0] = __floats2half2_rn(Cs[r][c4 + 0], Cs[r][c4 + 1]);
        pk.h2[1] = __floats2half2_rn(Cs[r][c4 + 2], Cs[r][c4 + 3]);
        *(uint2*)&out[outBase + (size_t)r * D + c4] = pk.u;
    }
}

// Layer-1 GEMM: fp32 A converted to fp16 in a smem staging tile; As/Cs union
// keeps static smem at 33.8 KB.
__global__ void __launch_bounds__(256)
k_gemm_wmma_f32(const float* __restrict__ A, const __half* __restrict__ W,
                __half* __restrict__ out) {
    __shared__ union SmemU {
        __half As[64][136];   // 17408 B
        float  Cs[64][132];   // 33792 B
    } sm;

    const int tid = threadIdx.x;
    const int wid = tid >> 5;
    const int wr  = wid >> 2;
    const int wc  = wid & 3;
    const int rowBase = blockIdx.x * 64;
    const int col0 = wc * 32;

    {
        int r  = tid >> 2;            // 0..63
        int c0 = (tid & 3) * 32;      // 0,32,64,96
        int grow = rowBase + r;
        if (grow < N_NODES) {
            const float* src = A + (size_t)grow * D + c0;
#pragma unroll
            for (int q = 0; q < 8; q++) {
                float4 v = *(const float4*)(src + q * 4);
                union { __half2 h2[2]; uint2 u; } pk;
                pk.h2[0] = __floats2half2_rn(v.x, v.y);
                pk.h2[1] = __floats2half2_rn(v.z, v.w);
                *(uint2*)&sm.As[r][c0 + q * 4] = pk.u;
            }
        } else {
            uint2 z = make_uint2(0, 0);
#pragma unroll
            for (int q = 0; q < 8; q++) *(uint2*)&sm.As[r][c0 + q * 4] = z;
        }
    }
    __syncthreads();

    wmma::fragment<wmma::accumulator, 16, 16, 16, float> acc[2][2];
#pragma unroll
    for (int i = 0; i < 2; i++)
#pragma unroll
        for (int j = 0; j < 2; j++) wmma::fill_fragment(acc[i][j], 0.0f);

#pragma unroll
    for (int k = 0; k < D; k += 16) {
        wmma::fragment<wmma::matrix_a, 16, 16, 16, __half, wmma::row_major> a0, a1;
        wmma::fragment<wmma::matrix_b, 16, 16, 16, __half, wmma::row_major> b0, b1;
        wmma::load_matrix_sync(a0, &sm.As[wr * 32][k], 136);
        wmma::load_matrix_sync(a1, &sm.As[wr * 32 + 16][k], 136);
        wmma::load_matrix_sync(b0, W + (size_t)k * D + col0, D);
        wmma::load_matrix_sync(b1, W + (size_t)k * D + col0 + 16, D);
        wmma::mma_sync(acc[0][0], a0, b0, acc[0][0]);
        wmma::mma_sync(acc[0][1], a0, b1, acc[0][1]);
        wmma::mma_sync(acc[1][0], a1, b0, acc[1][0]);
        wmma::mma_sync(acc[1][1], a1, b1, acc[1][1]);
    }
    __syncthreads();   // WAR fence: all As reads done before Cs overwrites the union

#pragma unroll
    for (int i = 0; i < 2; i++)
#pragma unroll
        for (int j = 0; j < 2; j++)
            wmma::store_matrix_sync(&sm.Cs[wr * 32 + i * 16][col0 + j * 16],
                                    acc[i][j], 132, wmma::mem_row_major);
    __syncthreads();

    const size_t outBase = (size_t)blockIdx.x * 64 * D;
    for (int g = tid; g < 64 * 32; g += 256) {
        int r  = g >> 5;
        int c4 = (g & 31) * 4;
        union { __half2 h2[2]; uint2 u; } pk;
        pk.h2[0] = __floats2half2_rn(sm.Cs[r][c4 + 0], sm.Cs[r][c4 + 1]);
        pk.h2[1] = __floats2half2_rn(sm.Cs[r][c4 + 2], sm.Cs[r][c4 + 3]);
        *(uint2*)&out[outBase + (size_t)r * D + c4] = pk.u;
    }
}

// ---------------------------------------------------------------------------
__device__ __forceinline__ float4 ld_row4(const __half* __restrict__ xs, int r, int c4) {
    uint2 u = __ldg((const uint2*)(xs + (size_t)r * D + c4));
    __half2 h0 = *(__half2*)&u.x;
    __half2 h1 = *(__half2*)&u.y;
    float2 a0 = __half22float2(h0);
    float2 a1 = __half22float2(h1);
    return make_float4(a0.x, a0.y, a1.x, a1.y);
}

// Gather (R12-proven form): one warp per node, 32 lanes x 8 B, 4 edges in
// flight, fp32 accumulation over fp16 messages. Reads padded buckets.
// SRC_SCALE: multiply each message by dinv[src].
// OUT_HALF : write fp16(result * dinv[node]) as next layer's GEMM input.
template <bool SRC_SCALE, bool OUT_HALF>
__global__ void k_gather(const __half* __restrict__ xs, const float* __restrict__ b,
                         const float* __restrict__ a, float* __restrict__ outf,
                         __half* __restrict__ outh) {
    int node = (blockIdx.x * blockDim.x + threadIdx.x) >> 5;
    int lane = threadIdx.x & 31;
    if (node >= N_NODES) return;
    const int c4 = lane * 4;
    const float di = g_dinv[node];

    float4 self = ld_row4(xs, node, c4);   // self loop
    float sw = SRC_SCALE ? di : 1.0f;
    float4 acc = make_float4(self.x * sw, self.y * sw, self.z * sw, self.w * sw);

    const int s = node * CAP;
    const int e = s + g_cur[node];
    int i = s;
    for (; i + 4 <= e; i += 4) {
        int r0 = __ldg(&g_bkt[i]);
        int r1 = __ldg(&g_bkt[i + 1]);
        int r2 = __ldg(&g_bkt[i + 2]);
        int r3 = __ldg(&g_bkt[i + 3]);
        float4 v0 = ld_row4(xs, r0, c4);
        float4 v1 = ld_row4(xs, r1, c4);
        float4 v2 = ld_row4(xs, r2, c4);
        float4 v3 = ld_row4(xs, r3, c4);
        if (SRC_SCALE) {
            float w0 = __ldg(&g_dinv[r0]);
            float w1 = __ldg(&g_dinv[r1]);
            float w2 = __ldg(&g_dinv[r2]);
            float w3 = __ldg(&g_dinv[r3]);
            acc.x = fmaf(v0.x, w0, fmaf(v1.x, w1, fmaf(v2.x, w2, fmaf(v3.x, w3, acc.x))));
            acc.y = fmaf(v0.y, w0, fmaf(v1.y, w1, fmaf(v2.y, w2, fmaf(v3.y, w3, acc.y))));
            acc.z = fmaf(v0.z, w0, fmaf(v1.z, w1, fmaf(v2.z, w2, fmaf(v3.z, w3, acc.z))));
            acc.w = fmaf(v0.w, w0, fmaf(v1.w, w1, fmaf(v2.w, w2, fmaf(v3.w, w3, acc.w))));
        } else {
            acc.x += (v0.x + v1.x) + (v2.x + v3.x);
            acc.y += (v0.y + v1.y) + (v2.y + v3.y);
            acc.z += (v0.z + v1.z) + (v2.z + v3.z);
            acc.w += (v0.w + v1.w) + (v2.w + v3.w);
        }
    }
    for (; i < e; i++) {
        int r0 = __ldg(&g_bkt[i]);
        float4 v0 = ld_row4(xs, r0, c4);
        float w0 = SRC_SCALE ? __ldg(&g_dinv[r0]) : 1.0f;
        acc.x = fmaf(v0.x, w0, acc.x);
        acc.y = fmaf(v0.y, w0, acc.y);
        acc.z = fmaf(v0.z, w0, acc.z);
        acc.w = fmaf(v0.w, w0, acc.w);
    }

    float4 bb = *(const float4*)&b[c4];
    float4 aa = *(const float4*)&a[c4];
    float4 o;
    o.x = fmaf(di, acc.x, bb.x); o.x = (o.x >= 0.f) ? o.x : aa.x * o.x;
    o.y = fmaf(di, acc.y, bb.y); o.y = (o.y >= 0.f) ? o.y : aa.y * o.y;
    o.z = fmaf(di, acc.z, bb.z); o.z = (o.z >= 0.f) ? o.z : aa.z * o.z;
    o.w = fmaf(di, acc.w, bb.w); o.w = (o.w >= 0.f) ? o.w : aa.w * o.w;

    if (OUT_HALF) {
        union { __half2 h2[2]; uint2 u; } pk;
        pk.h2[0] = __floats2half2_rn(o.x * di, o.y * di);
        pk.h2[1] = __floats2half2_rn(o.z * di, o.w * di);
        *(uint2*)&outh[(size_t)node * D + c4] = pk.u;
    } else {
        *(float4*)&outf[(size_t)node * D + c4] = o;
    }
}

// ---------------------------------------------------------------------------
extern "C" void kernel_launch(void* const* d_in, const int* in_sizes, int n_in,
                              void* d_out, int out_size) {
    const float* x  = (const float*)d_in[0];
    const int*   ei = (const int*)  d_in[1];
    const float* W1 = (const float*)d_in[2];
    const float* b1 = (const float*)d_in[3];
    const float* a1 = (const float*)d_in[4];
    const float* W2 = (const float*)d_in[5];
    const float* b2 = (const float*)d_in[6];
    const float* a2 = (const float*)d_in[7];
    float* out = (float*)d_out;

    const int4* row4 = (const int4*)ei;               // edge_index[0] = sources
    const int4* col4 = (const int4*)(ei + N_EDGES);   // edge_index[1] = targets

    __half *a_ptr, *xs_ptr, *w1_ptr, *w2_ptr;  int *cur_ptr;
    cudaGetSymbolAddress((void**)&a_ptr,   g_a);
    cudaGetSymbolAddress((void**)&xs_ptr,  g_xsh);
    cudaGetSymbolAddress((void**)&w1_ptr,  g_w1);
    cudaGetSymbolAddress((void**)&w2_ptr,  g_w2);
    cudaGetSymbolAddress((void**)&cur_ptr, g_cur);

    // one-time stream/event setup (host resources only; created on the first,
    // uncaptured call — never during graph capture)
    static cudaStream_t s_side = nullptr;
    static cudaEvent_t  ev_fork = nullptr, ev_join = nullptr;
    if (s_side == nullptr)  cudaStreamCreateWithFlags(&s_side, cudaStreamNonBlocking);
    if (ev_fork == nullptr) cudaEventCreateWithFlags(&ev_fork, cudaEventDisableTiming);
    if (ev_join == nullptr) cudaEventCreateWithFlags(&ev_join, cudaEventDisableTiming);

    const int e4blocks      = (N_EDGES / 4 + 255) / 256;
    const int gemm_blocks   = N_PAD / 64;   // 782
    const int gather_blocks = (N_NODES * 32 + 255) / 256;

    // ---- fork: bucket build on side stream (no hist, no scan) ----
    cudaEventRecord(ev_fork, 0);
    cudaStreamWaitEvent(s_side, ev_fork, 0);
    cudaMemsetAsync(cur_ptr, 0, N_NODES * sizeof(int), s_side);
    k_bucket<<<e4blocks, 256, 0, s_side>>>(row4, col4);
    k_dinv  <<<(N_NODES + 255) / 256, 256, 0, s_side>>>();
    cudaEventRecord(ev_join, s_side);

    // ---- main stream: weight convert + layer-1 GEMM (no dinv needed) ----
    k_conv_w       <<<(D * D + 255) / 256, 256>>>(W1, W2);
    k_gemm_wmma_f32<<<gemm_blocks, 256>>>(x, w1_ptr, xs_ptr);

    // ---- join: gather-1 needs buckets + dinv + messages ----
    cudaStreamWaitEvent(0, ev_join, 0);
    k_gather<true, true>  <<<gather_blocks, 256>>>(xs_ptr, b1, a1, nullptr, a_ptr);

    // ---- layer 2 (serial on main stream; xs reuse is safe) ----
    k_gemm_wmma<<<gemm_blocks, 256>>>(a_ptr, w2_ptr, xs_ptr);
    k_gather<false, false><<<gather_blocks, 256>>>(xs_ptr, b2, a2, out, nullptr);
}

// round 16
// speedup vs baseline: 1.4839x; 1.2646x over previous
#include <cuda_runtime.h>
#include <cuda_fp16.h>
#include <mma.h>

using namespace nvcuda;

#define N_NODES 50000
#define N_EDGES 800000
#define D 128
#define N_PAD 50048              // 782 * 64, padded row count for guard-free GEMM
#define CAP 96                   // bucket capacity per node (deg ~ Poisson(16))

#define AS_STRIDE 136            // halfs per A-tile row (272 B: 16B-aligned, 32B frag rows)
#define WS_STRIDE 136
#define AS_HALFS  (64 * AS_STRIDE)
#define WS_HALFS  (128 * WS_STRIDE)
#define GEMM_SMEM ((AS_HALFS + WS_HALFS) * 2)   // 52224 B dynamic smem

// ---- scratch (device globals; no allocation allowed) ----
__device__ __half g_a  [N_PAD * D];     // 12.8 MB: layer-2 GEMM input (pre-scaled by dinv)
__device__ __half g_xsh[N_PAD * D];     // 12.8 MB: GEMM output (messages)
__device__ __half g_w1 [D * D];
__device__ __half g_w2 [D * D];
__device__ float  g_dinv[N_NODES];
__device__ int    g_cur [N_NODES];      // per-node incoming-edge count (atomic cursor)
__device__ int    g_bkt [N_NODES * CAP]; // 19.2 MB: padded buckets of source nodes

// ---------------------------------------------------------------------------
// Single-pass bucket build: no histogram, no scan.
__global__ void k_bucket(const int4* __restrict__ row4, const int4* __restrict__ col4) {
    int i = blockIdx.x * blockDim.x + threadIdx.x;
    if (i < N_EDGES / 4) {
        int4 r = __ldg(&row4[i]);
        int4 c = __ldg(&col4[i]);
        g_bkt[c.x * CAP + atomicAdd(&g_cur[c.x], 1)] = r.x;
        g_bkt[c.y * CAP + atomicAdd(&g_cur[c.y], 1)] = r.y;
        g_bkt[c.z * CAP + atomicAdd(&g_cur[c.z], 1)] = r.z;
        g_bkt[c.w * CAP + atomicAdd(&g_cur[c.w], 1)] = r.w;
    }
}

__global__ void k_dinv() {
    int i = blockIdx.x * blockDim.x + threadIdx.x;
    if (i < N_NODES)
        g_dinv[i] = rsqrtf((float)(g_cur[i] + 1));   // +1 self loop -> always > 0
}

// ---------------------------------------------------------------------------
__global__ void k_conv_w(const float* __restrict__ W1, const float* __restrict__ W2) {
    int i = blockIdx.x * blockDim.x + threadIdx.x;
    if (i < D * D) {
        g_w1[i] = __float2half_rn(W1[i]);
        g_w2[i] = __float2half_rn(W2[i]);
    }
}

// ---------------------------------------------------------------------------
// Unified tensor-core GEMM: out = A @ W, all fragment loads from SMEM.
// Block = 64 rows x 128 cols, 8 warps 2x4, warp tile 32x32.
// Dynamic smem: As[64][136] fp16 | Ws[128][136] fp16 (Cs[64][132] f32 overlays Ws).
// F32IN: A is fp32 (harness input x, row-guarded, converted while staging);
// else   A is fp16 from g_a (padded to N_PAD rows, guard-free uint4 copy).
template <bool F32IN>
__global__ void __launch_bounds__(256)
k_gemm(const void* __restrict__ Ain, const __half* __restrict__ W,
       __half* __restrict__ out) {
    extern __shared__ __half smp[];
    __half* As = smp;                     // 64 x AS_STRIDE
    __half* Ws = smp + AS_HALFS;          // 128 x WS_STRIDE
    float*  Cs = (float*)Ws;              // 64 x 132 overlay (33792 B <= 34816 B)

    const int tid = threadIdx.x;
    const int wid = tid >> 5;
    const int wr  = wid >> 2;             // 0..1
    const int wc  = wid & 3;              // 0..3
    const int rowBase = blockIdx.x * 64;
    const int col0 = wc * 32;

    // ---- stage W: 128x128 fp16, coalesced uint4 (each thread 8x 16B) ----
    for (int idx = tid; idx < 128 * 16; idx += 256) {
        int r  = idx >> 4;
        int c8 = (idx & 15) * 8;
        *(uint4*)&Ws[r * WS_STRIDE + c8] = *(const uint4*)&W[(size_t)r * D + c8];
    }

    // ---- stage A tile: 64x128 ----
    if (F32IN) {
        const float* A = (const float*)Ain;
        int r  = tid >> 2;                // 0..63
        int c0 = (tid & 3) * 32;          // 0,32,64,96
        int grow = rowBase + r;
        if (grow < N_NODES) {
            const float* src = A + (size_t)grow * D + c0;
#pragma unroll
            for (int q = 0; q < 8; q++) {
                float4 v = *(const float4*)(src + q * 4);
                union { __half2 h2[2]; uint2 u; } pk;
                pk.h2[0] = __floats2half2_rn(v.x, v.y);
                pk.h2[1] = __floats2half2_rn(v.z, v.w);
                *(uint2*)&As[r * AS_STRIDE + c0 + q * 4] = pk.u;
            }
        } else {
            uint2 z = make_uint2(0, 0);
#pragma unroll
            for (int q = 0; q < 8; q++) *(uint2*)&As[r * AS_STRIDE + c0 + q * 4] = z;
        }
    } else {
        const __half* A = (const __half*)Ain;
        for (int idx = tid; idx < 64 * 16; idx += 256) {
            int r  = idx >> 4;
            int c8 = (idx & 15) * 8;
            *(uint4*)&As[r * AS_STRIDE + c8] =
                *(const uint4*)&A[(size_t)(rowBase + r) * D + c8];
        }
    }
    __syncthreads();

    wmma::fragment<wmma::accumulator, 16, 16, 16, float> acc[2][2];
#pragma unroll
    for (int i = 0; i < 2; i++)
#pragma unroll
        for (int j = 0; j < 2; j++) wmma::fill_fragment(acc[i][j], 0.0f);

#pragma unroll
    for (int k = 0; k < D; k += 16) {
        wmma::fragment<wmma::matrix_a, 16, 16, 16, __half, wmma::row_major> a0, a1;
        wmma::fragment<wmma::matrix_b, 16, 16, 16, __half, wmma::row_major> b0, b1;
        wmma::load_matrix_sync(a0, &As[(wr * 32) * AS_STRIDE + k], AS_STRIDE);
        wmma::load_matrix_sync(a1, &As[(wr * 32 + 16) * AS_STRIDE + k], AS_STRIDE);
        wmma::load_matrix_sync(b0, &Ws[k * WS_STRIDE + col0], WS_STRIDE);
        wmma::load_matrix_sync(b1, &Ws[k * WS_STRIDE + col0 + 16], WS_STRIDE);
        wmma::mma_sync(acc[0][0], a0, b0, acc[0][0]);
        wmma::mma_sync(acc[0][1], a0, b1, acc[0][1]);
        wmma::mma_sync(acc[1][0], a1, b0, acc[1][0]);
        wmma::mma_sync(acc[1][1], a1, b1, acc[1][1]);
    }
    __syncthreads();   // WAR: all Ws fragment reads done before Cs overlays it

#pragma unroll
    for (int i = 0; i < 2; i++)
#pragma unroll
        for (int j = 0; j < 2; j++)
            wmma::store_matrix_sync(&Cs[(wr * 32 + i * 16) * 132 + col0 + j * 16],
                                    acc[i][j], 132, wmma::mem_row_major);
    __syncthreads();

    const size_t outBase = (size_t)blockIdx.x * 64 * D;
    for (int g = tid; g < 64 * 32; g += 256) {
        int r  = g >> 5;
        int c4 = (g & 31) * 4;
        union { __half2 h2[2]; uint2 u; } pk;
        pk.h2[0] = __floats2half2_rn(Cs[r * 132 + c4 + 0], Cs[r * 132 + c4 + 1]);
        pk.h2[1] = __floats2half2_rn(Cs[r * 132 + c4 + 2], Cs[r * 132 + c4 + 3]);
        *(uint2*)&out[outBase + (size_t)r * D + c4] = pk.u;
    }
}

// ---------------------------------------------------------------------------
__device__ __forceinline__ float4 ld_row4(const __half* __restrict__ xs, int r, int c4) {
    uint2 u = __ldg((const uint2*)(xs + (size_t)r * D + c4));
    __half2 h0 = *(__half2*)&u.x;
    __half2 h1 = *(__half2*)&u.y;
    float2 a0 = __half22float2(h0);
    float2 a1 = __half22float2(h1);
    return make_float4(a0.x, a0.y, a1.x, a1.y);
}

// Gather: one warp per node, 32 lanes x 8 B, 4 edges in flight, fp32 accum.
// SRC_SCALE: multiply each message by dinv[src].
// OUT_HALF : write fp16(result * dinv[node]) as next layer's GEMM input.
template <bool SRC_SCALE, bool OUT_HALF>
__global__ void k_gather(const __half* __restrict__ xs, const float* __restrict__ b,
                         const float* __restrict__ a, float* __restrict__ outf,
                         __half* __restrict__ outh) {
    int node = (blockIdx.x * blockDim.x + threadIdx.x) >> 5;
    int lane = threadIdx.x & 31;
    if (node >= N_NODES) return;
    const int c4 = lane * 4;
    const float di = g_dinv[node];

    float4 self = ld_row4(xs, node, c4);   // self loop
    float sw = SRC_SCALE ? di : 1.0f;
    float4 acc = make_float4(self.x * sw, self.y * sw, self.z * sw, self.w * sw);

    const int s = node * CAP;
    const int e = s + g_cur[node];
    int i = s;
    for (; i + 4 <= e; i += 4) {
        int r0 = __ldg(&g_bkt[i]);
        int r1 = __ldg(&g_bkt[i + 1]);
        int r2 = __ldg(&g_bkt[i + 2]);
        int r3 = __ldg(&g_bkt[i + 3]);
        float4 v0 = ld_row4(xs, r0, c4);
        float4 v1 = ld_row4(xs, r1, c4);
        float4 v2 = ld_row4(xs, r2, c4);
        float4 v3 = ld_row4(xs, r3, c4);
        if (SRC_SCALE) {
            float w0 = __ldg(&g_dinv[r0]);
            float w1 = __ldg(&g_dinv[r1]);
            float w2 = __ldg(&g_dinv[r2]);
            float w3 = __ldg(&g_dinv[r3]);
            acc.x = fmaf(v0.x, w0, fmaf(v1.x, w1, fmaf(v2.x, w2, fmaf(v3.x, w3, acc.x))));
            acc.y = fmaf(v0.y, w0, fmaf(v1.y, w1, fmaf(v2.y, w2, fmaf(v3.y, w3, acc.y))));
            acc.z = fmaf(v0.z, w0, fmaf(v1.z, w1, fmaf(v2.z, w2, fmaf(v3.z, w3, acc.z))));
            acc.w = fmaf(v0.w, w0, fmaf(v1.w, w1, fmaf(v2.w, w2, fmaf(v3.w, w3, acc.w))));
        } else {
            acc.x += (v0.x + v1.x) + (v2.x + v3.x);
            acc.y += (v0.y + v1.y) + (v2.y + v3.y);
            acc.z += (v0.z + v1.z) + (v2.z + v3.z);
            acc.w += (v0.w + v1.w) + (v2.w + v3.w);
        }
    }
    for (; i < e; i++) {
        int r0 = __ldg(&g_bkt[i]);
        float4 v0 = ld_row4(xs, r0, c4);
        float w0 = SRC_SCALE ? __ldg(&g_dinv[r0]) : 1.0f;
        acc.x = fmaf(v0.x, w0, acc.x);
        acc.y = fmaf(v0.y, w0, acc.y);
        acc.z = fmaf(v0.z, w0, acc.z);
        acc.w = fmaf(v0.w, w0, acc.w);
    }

    float4 bb = *(const float4*)&b[c4];
    float4 aa = *(const float4*)&a[c4];
    float4 o;
    o.x = fmaf(di, acc.x, bb.x); o.x = (o.x >= 0.f) ? o.x : aa.x * o.x;
    o.y = fmaf(di, acc.y, bb.y); o.y = (o.y >= 0.f) ? o.y : aa.y * o.y;
    o.z = fmaf(di, acc.z, bb.z); o.z = (o.z >= 0.f) ? o.z : aa.z * o.z;
    o.w = fmaf(di, acc.w, bb.w); o.w = (o.w >= 0.f) ? o.w : aa.w * o.w;

    if (OUT_HALF) {
        union { __half2 h2[2]; uint2 u; } pk;
        pk.h2[0] = __floats2half2_rn(o.x * di, o.y * di);
        pk.h2[1] = __floats2half2_rn(o.z * di, o.w * di);
        *(uint2*)&outh[(size_t)node * D + c4] = pk.u;
    } else {
        *(float4*)&outf[(size_t)node * D + c4] = o;
    }
}

// ---------------------------------------------------------------------------
extern "C" void kernel_launch(void* const* d_in, const int* in_sizes, int n_in,
                              void* d_out, int out_size) {
    const float* x  = (const float*)d_in[0];
    const int*   ei = (const int*)  d_in[1];
    const float* W1 = (const float*)d_in[2];
    const float* b1 = (const float*)d_in[3];
    const float* a1 = (const float*)d_in[4];
    const float* W2 = (const float*)d_in[5];
    const float* b2 = (const float*)d_in[6];
    const float* a2 = (const float*)d_in[7];
    float* out = (float*)d_out;

    const int4* row4 = (const int4*)ei;               // edge_index[0] = sources
    const int4* col4 = (const int4*)(ei + N_EDGES);   // edge_index[1] = targets

    __half *a_ptr, *xs_ptr, *w1_ptr, *w2_ptr;  int *cur_ptr;
    cudaGetSymbolAddress((void**)&a_ptr,   g_a);
    cudaGetSymbolAddress((void**)&xs_ptr,  g_xsh);
    cudaGetSymbolAddress((void**)&w1_ptr,  g_w1);
    cudaGetSymbolAddress((void**)&w2_ptr,  g_w2);
    cudaGetSymbolAddress((void**)&cur_ptr, g_cur);

    // one-time setup (host resources + func attributes; first call is uncaptured)
    static cudaStream_t s_side = nullptr;
    static cudaEvent_t  ev_fork = nullptr, ev_join = nullptr;
    static bool attr_done = false;
    if (s_side == nullptr)  cudaStreamCreateWithFlags(&s_side, cudaStreamNonBlocking);
    if (ev_fork == nullptr) cudaEventCreateWithFlags(&ev_fork, cudaEventDisableTiming);
    if (ev_join == nullptr) cudaEventCreateWithFlags(&ev_join, cudaEventDisableTiming);
    if (!attr_done) {
        cudaFuncSetAttribute(k_gemm<true>,
                             cudaFuncAttributeMaxDynamicSharedMemorySize, GEMM_SMEM);
        cudaFuncSetAttribute(k_gemm<false>,
                             cudaFuncAttributeMaxDynamicSharedMemorySize, GEMM_SMEM);
        attr_done = true;
    }

    const int e4blocks      = (N_EDGES / 4 + 255) / 256;
    const int gemm_blocks   = N_PAD / 64;   // 782
    const int gather_blocks = (N_NODES * 32 + 255) / 256;

    // ---- fork: bucket build on side stream (no hist, no scan) ----
    cudaEventRecord(ev_fork, 0);
    cudaStreamWaitEvent(s_side, ev_fork, 0);
    cudaMemsetAsync(cur_ptr, 0, N_NODES * sizeof(int), s_side);
    k_bucket<<<e4blocks, 256, 0, s_side>>>(row4, col4);
    k_dinv  <<<(N_NODES + 255) / 256, 256, 0, s_side>>>();
    cudaEventRecord(ev_join, s_side);

    // ---- main stream: weight convert + layer-1 GEMM (no dinv needed) ----
    k_conv_w     <<<(D * D + 255) / 256, 256>>>(W1, W2);
    k_gemm<true> <<<gemm_blocks, 256, GEMM_SMEM>>>(x, w1_ptr, xs_ptr);

    // ---- join: gather-1 needs buckets + dinv + messages ----
    cudaStreamWaitEvent(0, ev_join, 0);
    k_gather<true, true>  <<<gather_blocks, 256>>>(xs_ptr, b1, a1, nullptr, a_ptr);

    // ---- layer 2 (serial on main stream; xs reuse is safe) ----
    k_gemm<false><<<gemm_blocks, 256, GEMM_SMEM>>>(a_ptr, w2_ptr, xs_ptr);
    k_gather<false, false><<<gather_blocks, 256>>>(xs_ptr, b2, a2, out, nullptr);
}